// round 2
// baseline (speedup 1.0000x reference)
#include <cuda_runtime.h>
#include <cuda_bf16.h>
#include <cstdint>
#include <math.h>

#define T_TOK 2048
#define DIM 1024
#define HID 4096
#define NE 8

#define BM 64
#define BN 64
#define BK 32
#define BKP 36  // padded k-stride (bf16 elems): 72B rows -> good bank spread, 8B aligned

// -------- scratch (device globals; no allocation allowed) --------
__device__ int g_cnt[NE];
__device__ int g_list[NE * T_TOK];
__device__ float g_wpair[2 * T_TOK];
__device__ __align__(256) float g_h[(size_t)2 * T_TOK * HID];    // 4096 x 4096 = 64 MB
__device__ __align__(256) float g_ye[(size_t)2 * T_TOK * DIM];   // 4096 x 1024 = 16 MB

// ---------------- helpers ----------------
__device__ __forceinline__ void mma_bf16(float c[4], const uint32_t a[4], const uint32_t b[2]) {
  asm volatile(
      "mma.sync.aligned.m16n8k16.row.col.f32.bf16.bf16.f32 "
      "{%0,%1,%2,%3}, {%4,%5,%6,%7}, {%8,%9}, {%0,%1,%2,%3};\n"
      : "+f"(c[0]), "+f"(c[1]), "+f"(c[2]), "+f"(c[3])
      : "r"(a[0]), "r"(a[1]), "r"(a[2]), "r"(a[3]), "r"(b[0]), "r"(b[1]));
}

// split fp32 -> bf16 hi + bf16 lo, store 4 consecutive elems
__device__ __forceinline__ void split_store(__nv_bfloat16* ph, __nv_bfloat16* pl, float4 v) {
  float vs[4] = {v.x, v.y, v.z, v.w};
#pragma unroll
  for (int i = 0; i < 4; i++) {
    __nv_bfloat16 hb = __float2bfloat16(vs[i]);
    ph[i] = hb;
    pl[i] = __float2bfloat16(vs[i] - __bfloat162float(hb));
  }
}

// ---------------- kernels ----------------
__global__ void reset_kernel() {
  if (threadIdx.x < NE) g_cnt[threadIdx.x] = 0;
}

__global__ void gate_kernel(const float* __restrict__ x, const float* __restrict__ gw) {
  int t = blockIdx.x * 4 + (threadIdx.x >> 5);
  int lane = threadIdx.x & 31;
  float p[NE];
#pragma unroll
  for (int e = 0; e < NE; e++) p[e] = 0.f;
  const float* xr = x + (size_t)t * DIM;
  for (int j = lane; j < DIM; j += 32) {
    float xv = xr[j];
#pragma unroll
    for (int e = 0; e < NE; e++) p[e] += xv * gw[e * DIM + j];
  }
#pragma unroll
  for (int off = 16; off > 0; off >>= 1) {
#pragma unroll
    for (int e = 0; e < NE; e++) p[e] += __shfl_xor_sync(0xffffffffu, p[e], off);
  }
  if (lane == 0) {
    int i0 = 0;
    float v0 = p[0];
#pragma unroll
    for (int e = 1; e < NE; e++)
      if (p[e] > v0) { v0 = p[e]; i0 = e; }
    int i1 = -1;
    float v1 = -3.0e38f;
#pragma unroll
    for (int e = 0; e < NE; e++)
      if (e != i0 && p[e] > v1) { v1 = p[e]; i1 = e; }
    float e1 = expf(v1 - v0);
    float s = 1.f + e1;
    float w0 = 1.f / s, w1v = e1 / s;
    int pos = atomicAdd(&g_cnt[i0], 1);
    g_list[i0 * T_TOK + pos] = t * 2;
    g_wpair[t * 2] = w0;
    pos = atomicAdd(&g_cnt[i1], 1);
    g_list[i1 * T_TOK + pos] = t * 2 + 1;
    g_wpair[t * 2 + 1] = w1v;
  }
}

// FFN1: h[r, n] = silu(x[tok]·w1[e,n,:]) * (x[tok]·w3[e,n,:])  (grouped by expert, gathered rows)
__global__ __launch_bounds__(128) void ffn1_kernel(const float* __restrict__ x,
                                                   const float* __restrict__ w1,
                                                   const float* __restrict__ w3) {
  int e = blockIdx.z;
  int ne = g_cnt[e];
  int m0 = blockIdx.y * BM;
  if (m0 >= ne) return;
  int n0 = blockIdx.x * BN;

  __shared__ __nv_bfloat16 sAh[BM][BKP], sAl[BM][BKP];
  __shared__ __nv_bfloat16 sB1h[BN][BKP], sB1l[BN][BKP];
  __shared__ __nv_bfloat16 sB3h[BN][BKP], sB3l[BN][BKP];
  __shared__ int sRow[BM];

  int tid = threadIdx.x;
  if (tid < BM) {
    int i = m0 + tid;
    sRow[tid] = (i < ne) ? g_list[e * T_TOK + i] : -1;
  }

  float acc1[2][4][4], acc3[2][4][4];
#pragma unroll
  for (int a = 0; a < 2; a++)
#pragma unroll
    for (int b = 0; b < 4; b++)
#pragma unroll
      for (int c = 0; c < 4; c++) { acc1[a][b][c] = 0.f; acc3[a][b][c] = 0.f; }

  int warp = tid >> 5, lane = tid & 31;
  int wm = warp >> 1, wn = warp & 1;
  int gg = lane >> 2, q = lane & 3;

  const float* w1b = w1 + ((size_t)e * HID + n0) * DIM;
  const float* w3b = w3 + ((size_t)e * HID + n0) * DIM;

  for (int k0 = 0; k0 < DIM; k0 += BK) {
    __syncthreads();
#pragma unroll
    for (int j = 0; j < 4; j++) {
      int idx = j * 128 + tid;
      int row = idx >> 3, cv = idx & 7;
      int r = sRow[row];
      float4 v = make_float4(0.f, 0.f, 0.f, 0.f);
      if (r >= 0) v = *(const float4*)(x + (size_t)(r >> 1) * DIM + k0 + cv * 4);
      split_store(&sAh[row][cv * 4], &sAl[row][cv * 4], v);
      float4 v1 = *(const float4*)(w1b + (size_t)row * DIM + k0 + cv * 4);
      split_store(&sB1h[row][cv * 4], &sB1l[row][cv * 4], v1);
      float4 v3 = *(const float4*)(w3b + (size_t)row * DIM + k0 + cv * 4);
      split_store(&sB3h[row][cv * 4], &sB3l[row][cv * 4], v3);
    }
    __syncthreads();
#pragma unroll
    for (int ks = 0; ks < 2; ks++) {
      int kc = ks * 16;
      uint32_t ah[2][4], al[2][4];
#pragma unroll
      for (int mf = 0; mf < 2; mf++) {
        int rb = wm * 32 + mf * 16;
        ah[mf][0] = *(const uint32_t*)&sAh[rb + gg][kc + 2 * q];
        ah[mf][1] = *(const uint32_t*)&sAh[rb + gg + 8][kc + 2 * q];
        ah[mf][2] = *(const uint32_t*)&sAh[rb + gg][kc + 2 * q + 8];
        ah[mf][3] = *(const uint32_t*)&sAh[rb + gg + 8][kc + 2 * q + 8];
        al[mf][0] = *(const uint32_t*)&sAl[rb + gg][kc + 2 * q];
        al[mf][1] = *(const uint32_t*)&sAl[rb + gg + 8][kc + 2 * q];
        al[mf][2] = *(const uint32_t*)&sAl[rb + gg][kc + 2 * q + 8];
        al[mf][3] = *(const uint32_t*)&sAl[rb + gg + 8][kc + 2 * q + 8];
      }
#pragma unroll
      for (int nf = 0; nf < 4; nf++) {
        int nb = wn * 32 + nf * 8 + gg;
        uint32_t b1h[2], b1l[2], b3h[2], b3l[2];
        b1h[0] = *(const uint32_t*)&sB1h[nb][kc + 2 * q];
        b1h[1] = *(const uint32_t*)&sB1h[nb][kc + 2 * q + 8];
        b1l[0] = *(const uint32_t*)&sB1l[nb][kc + 2 * q];
        b1l[1] = *(const uint32_t*)&sB1l[nb][kc + 2 * q + 8];
        b3h[0] = *(const uint32_t*)&sB3h[nb][kc + 2 * q];
        b3h[1] = *(const uint32_t*)&sB3h[nb][kc + 2 * q + 8];
        b3l[0] = *(const uint32_t*)&sB3l[nb][kc + 2 * q];
        b3l[1] = *(const uint32_t*)&sB3l[nb][kc + 2 * q + 8];
#pragma unroll
        for (int mf = 0; mf < 2; mf++) {
          mma_bf16(acc1[mf][nf], ah[mf], b1h);
          mma_bf16(acc1[mf][nf], al[mf], b1h);
          mma_bf16(acc1[mf][nf], ah[mf], b1l);
          mma_bf16(acc3[mf][nf], ah[mf], b3h);
          mma_bf16(acc3[mf][nf], al[mf], b3h);
          mma_bf16(acc3[mf][nf], ah[mf], b3l);
        }
      }
    }
  }
  // epilogue: h = silu(a1) * a3
#pragma unroll
  for (int mf = 0; mf < 2; mf++) {
#pragma unroll
    for (int half = 0; half < 2; half++) {
      int rloc = wm * 32 + mf * 16 + gg + half * 8;
      int r = sRow[rloc];
      if (r < 0) continue;
      float* hrow = g_h + (size_t)r * HID + n0 + wn * 32;
#pragma unroll
      for (int nf = 0; nf < 4; nf++) {
        float a1 = acc1[mf][nf][half * 2 + 0];
        float b1 = acc1[mf][nf][half * 2 + 1];
        float a3 = acc3[mf][nf][half * 2 + 0];
        float b3 = acc3[mf][nf][half * 2 + 1];
        float h0 = (a1 / (1.f + expf(-a1))) * a3;
        float h1 = (b1 / (1.f + expf(-b1))) * b3;
        *(float2*)(hrow + nf * 8 + 2 * q) = make_float2(h0, h1);
      }
    }
  }
}

// FFN2: ye[r, n] = h[r,:]·w2[e,n,:]
__global__ __launch_bounds__(128) void ffn2_kernel(const float* __restrict__ w2) {
  int e = blockIdx.z;
  int ne = g_cnt[e];
  int m0 = blockIdx.y * BM;
  if (m0 >= ne) return;
  int n0 = blockIdx.x * BN;

  __shared__ __nv_bfloat16 sAh[BM][BKP], sAl[BM][BKP];
  __shared__ __nv_bfloat16 sBh[BN][BKP], sBl[BN][BKP];
  __shared__ int sRow[BM];

  int tid = threadIdx.x;
  if (tid < BM) {
    int i = m0 + tid;
    sRow[tid] = (i < ne) ? g_list[e * T_TOK + i] : -1;
  }

  float acc[2][4][4];
#pragma unroll
  for (int a = 0; a < 2; a++)
#pragma unroll
    for (int b = 0; b < 4; b++)
#pragma unroll
      for (int c = 0; c < 4; c++) acc[a][b][c] = 0.f;

  int warp = tid >> 5, lane = tid & 31;
  int wm = warp >> 1, wn = warp & 1;
  int gg = lane >> 2, q = lane & 3;

  const float* w2b = w2 + ((size_t)e * DIM + n0) * HID;

  for (int k0 = 0; k0 < HID; k0 += BK) {
    __syncthreads();
#pragma unroll
    for (int j = 0; j < 4; j++) {
      int idx = j * 128 + tid;
      int row = idx >> 3, cv = idx & 7;
      int r = sRow[row];
      float4 v = make_float4(0.f, 0.f, 0.f, 0.f);
      if (r >= 0) v = *(const float4*)(g_h + (size_t)r * HID + k0 + cv * 4);
      split_store(&sAh[row][cv * 4], &sAl[row][cv * 4], v);
      float4 vb = *(const float4*)(w2b + (size_t)row * HID + k0 + cv * 4);
      split_store(&sBh[row][cv * 4], &sBl[row][cv * 4], vb);
    }
    __syncthreads();
#pragma unroll
    for (int ks = 0; ks < 2; ks++) {
      int kc = ks * 16;
      uint32_t ah[2][4], al[2][4];
#pragma unroll
      for (int mf = 0; mf < 2; mf++) {
        int rb = wm * 32 + mf * 16;
        ah[mf][0] = *(const uint32_t*)&sAh[rb + gg][kc + 2 * q];
        ah[mf][1] = *(const uint32_t*)&sAh[rb + gg + 8][kc + 2 * q];
        ah[mf][2] = *(const uint32_t*)&sAh[rb + gg][kc + 2 * q + 8];
        ah[mf][3] = *(const uint32_t*)&sAh[rb + gg + 8][kc + 2 * q + 8];
        al[mf][0] = *(const uint32_t*)&sAl[rb + gg][kc + 2 * q];
        al[mf][1] = *(const uint32_t*)&sAl[rb + gg + 8][kc + 2 * q];
        al[mf][2] = *(const uint32_t*)&sAl[rb + gg][kc + 2 * q + 8];
        al[mf][3] = *(const uint32_t*)&sAl[rb + gg + 8][kc + 2 * q + 8];
      }
#pragma unroll
      for (int nf = 0; nf < 4; nf++) {
        int nb = wn * 32 + nf * 8 + gg;
        uint32_t bh[2], bl[2];
        bh[0] = *(const uint32_t*)&sBh[nb][kc + 2 * q];
        bh[1] = *(const uint32_t*)&sBh[nb][kc + 2 * q + 8];
        bl[0] = *(const uint32_t*)&sBl[nb][kc + 2 * q];
        bl[1] = *(const uint32_t*)&sBl[nb][kc + 2 * q + 8];
#pragma unroll
        for (int mf = 0; mf < 2; mf++) {
          mma_bf16(acc[mf][nf], ah[mf], bh);
          mma_bf16(acc[mf][nf], al[mf], bh);
          mma_bf16(acc[mf][nf], ah[mf], bl);
        }
      }
    }
  }
#pragma unroll
  for (int mf = 0; mf < 2; mf++) {
#pragma unroll
    for (int half = 0; half < 2; half++) {
      int rloc = wm * 32 + mf * 16 + gg + half * 8;
      int r = sRow[rloc];
      if (r < 0) continue;
      float* yrow = g_ye + (size_t)r * DIM + n0 + wn * 32;
#pragma unroll
      for (int nf = 0; nf < 4; nf++) {
        *(float2*)(yrow + nf * 8 + 2 * q) =
            make_float2(acc[mf][nf][half * 2 + 0], acc[mf][nf][half * 2 + 1]);
      }
    }
  }
}

__global__ void combine_kernel(float* __restrict__ out) {
  int idx = blockIdx.x * 256 + threadIdx.x;
  int t = idx >> 10;
  int d = idx & 1023;
  out[idx] = g_wpair[2 * t] * g_ye[(size_t)(2 * t) * DIM + d] +
             g_wpair[2 * t + 1] * g_ye[(size_t)(2 * t + 1) * DIM + d];
}

// ---------------- launch ----------------
extern "C" void kernel_launch(void* const* d_in, const int* in_sizes, int n_in,
                              void* d_out, int out_size) {
  const float* x = (const float*)d_in[0];
  const float* gw = (const float*)d_in[1];
  const float* w1 = (const float*)d_in[2];
  const float* w2 = (const float*)d_in[3];
  const float* w3 = (const float*)d_in[4];
  float* out = (float*)d_out;

  reset_kernel<<<1, 32>>>();
  gate_kernel<<<T_TOK / 4, 128>>>(x, gw);
  ffn1_kernel<<<dim3(HID / BN, T_TOK / BM, NE), 128>>>(x, w1, w3);
  ffn2_kernel<<<dim3(DIM / BN, T_TOK / BM, NE), 128>>>(w2);
  combine_kernel<<<(T_TOK * DIM) / 256, 256>>>(out);
}

// round 5
// speedup vs baseline: 2.0617x; 2.0617x over previous
#include <cuda_runtime.h>
#include <cuda_bf16.h>
#include <cstdint>
#include <math.h>

#define T_TOK 2048
#define DIM 1024
#define HID 4096
#define NE 8

#define BM 64
#define BN 64
#define BK 32
#define BKP 40  // padded k-stride (bf16): 80B rows -> conflict-free ldmatrix (r*20 mod 32 disjoint)

// -------- scratch (device globals; no allocation allowed) --------
__device__ int g_cnt[NE];
__device__ int g_list[NE * T_TOK];
__device__ float g_wpair[2 * T_TOK];
__device__ __align__(256) __nv_bfloat16 g_hh[(size_t)2 * T_TOK * HID];  // h hi, 32MB
__device__ __align__(256) __nv_bfloat16 g_hl[(size_t)2 * T_TOK * HID];  // h lo, 32MB
__device__ __align__(256) float g_ye[(size_t)2 * T_TOK * DIM];          // 16MB

// ---------------- helpers ----------------
__device__ __forceinline__ void mma16816(float c[4], const uint32_t a[4], uint32_t b0,
                                         uint32_t b1) {
  asm volatile(
      "mma.sync.aligned.m16n8k16.row.col.f32.bf16.bf16.f32 "
      "{%0,%1,%2,%3}, {%4,%5,%6,%7}, {%8,%9}, {%0,%1,%2,%3};\n"
      : "+f"(c[0]), "+f"(c[1]), "+f"(c[2]), "+f"(c[3])
      : "r"(a[0]), "r"(a[1]), "r"(a[2]), "r"(a[3]), "r"(b0), "r"(b1));
}

__device__ __forceinline__ void ldsm4(uint32_t r[4], const __nv_bfloat16* p) {
  uint32_t a = (uint32_t)__cvta_generic_to_shared(p);
  asm volatile("ldmatrix.sync.aligned.m8n8.x4.shared.b16 {%0,%1,%2,%3}, [%4];"
               : "=r"(r[0]), "=r"(r[1]), "=r"(r[2]), "=r"(r[3])
               : "r"(a));
}

// pack (x0,x1) -> bf16x2 hi word + bf16x2 residual word
__device__ __forceinline__ void split2(float x0, float x1, uint32_t& hi, uint32_t& lo) {
  asm("cvt.rn.bf16x2.f32 %0, %1, %2;" : "=r"(hi) : "f"(x1), "f"(x0));
  float h0 = __uint_as_float(hi << 16);
  float h1 = __uint_as_float(hi & 0xffff0000u);
  float l0 = x0 - h0, l1 = x1 - h1;
  asm("cvt.rn.bf16x2.f32 %0, %1, %2;" : "=r"(lo) : "f"(l1), "f"(l0));
}

__device__ __forceinline__ void split4(float4 v, uint2& hi, uint2& lo) {
  uint32_t h0, l0, h1, l1;
  split2(v.x, v.y, h0, l0);
  split2(v.z, v.w, h1, l1);
  hi = make_uint2(h0, h1);
  lo = make_uint2(l0, l1);
}

// ---------------- small kernels ----------------
__global__ void reset_kernel() {
  if (threadIdx.x < NE) g_cnt[threadIdx.x] = 0;
}

__global__ void gate_kernel(const float* __restrict__ x, const float* __restrict__ gw) {
  int t = blockIdx.x * 4 + (threadIdx.x >> 5);
  int lane = threadIdx.x & 31;
  float p[NE];
#pragma unroll
  for (int e = 0; e < NE; e++) p[e] = 0.f;
  const float* xr = x + (size_t)t * DIM;
  for (int j = lane; j < DIM; j += 32) {
    float xv = xr[j];
#pragma unroll
    for (int e = 0; e < NE; e++) p[e] += xv * gw[e * DIM + j];
  }
#pragma unroll
  for (int off = 16; off > 0; off >>= 1) {
#pragma unroll
    for (int e = 0; e < NE; e++) p[e] += __shfl_xor_sync(0xffffffffu, p[e], off);
  }
  if (lane == 0) {
    int i0 = 0;
    float v0 = p[0];
#pragma unroll
    for (int e = 1; e < NE; e++)
      if (p[e] > v0) { v0 = p[e]; i0 = e; }
    int i1 = -1;
    float v1 = -3.0e38f;
#pragma unroll
    for (int e = 0; e < NE; e++)
      if (e != i0 && p[e] > v1) { v1 = p[e]; i1 = e; }
    float e1 = expf(v1 - v0);
    float s = 1.f + e1;
    float w0 = 1.f / s, w1v = e1 / s;
    int pos = atomicAdd(&g_cnt[i0], 1);
    g_list[i0 * T_TOK + pos] = t * 2;
    g_wpair[t * 2] = w0;
    pos = atomicAdd(&g_cnt[i1], 1);
    g_list[i1 * T_TOK + pos] = t * 2 + 1;
    g_wpair[t * 2 + 1] = w1v;
  }
}

// ---------------- FFN1: h = silu(x w1^T) * (x w3^T), grouped by expert ----------------
__global__ __launch_bounds__(128, 2) void ffn1_kernel(const float* __restrict__ x,
                                                      const float* __restrict__ w1,
                                                      const float* __restrict__ w3) {
  int e = blockIdx.z;
  int ne = g_cnt[e];
  int m0 = blockIdx.y * BM;
  if (m0 >= ne) return;
  int n0 = blockIdx.x * BN;

  __shared__ __align__(16) __nv_bfloat16 sAh[BM][BKP], sAl[BM][BKP];
  __shared__ __align__(16) __nv_bfloat16 sB1h[BN][BKP], sB1l[BN][BKP];
  __shared__ __align__(16) __nv_bfloat16 sB3h[BN][BKP], sB3l[BN][BKP];
  __shared__ int sRow[BM];

  int tid = threadIdx.x;
  int lane = tid & 31, warp = tid >> 5;
  int wm = warp >> 1, wn = warp & 1;

  if (tid < BM) {
    int i = m0 + tid;
    sRow[tid] = (i < ne) ? g_list[e * T_TOK + i] : -1;
  }
  __syncthreads();

  // ldmatrix per-lane offsets
  int arow = (lane & 7) + ((lane >> 3) & 1) * 8;
  int ak = (lane >> 4) * 8;
  int brow = (lane & 7) + (lane >> 4) * 8;
  int bk = ((lane >> 3) & 1) * 8;

  const float* w1b = w1 + ((size_t)e * HID + n0) * DIM;
  const float* w3b = w3 + ((size_t)e * HID + n0) * DIM;

  int r0 = tid >> 3, cv = tid & 7;

  float acc1[2][4][4], acc3[2][4][4];
#pragma unroll
  for (int a = 0; a < 2; a++)
#pragma unroll
    for (int b = 0; b < 4; b++)
#pragma unroll
      for (int c = 0; c < 4; c++) { acc1[a][b][c] = 0.f; acc3[a][b][c] = 0.f; }

  float4 rA[4], rB1[4], rB3[4];
#pragma unroll
  for (int j = 0; j < 4; j++) {
    int row = j * 16 + r0;
    int r = sRow[row];
    rA[j] = (r >= 0) ? *(const float4*)(x + (size_t)(r >> 1) * DIM + cv * 4)
                     : make_float4(0.f, 0.f, 0.f, 0.f);
    rB1[j] = *(const float4*)(w1b + (size_t)row * DIM + cv * 4);
    rB3[j] = *(const float4*)(w3b + (size_t)row * DIM + cv * 4);
  }

  for (int k0 = 0; k0 < DIM; k0 += BK) {
    __syncthreads();
#pragma unroll
    for (int j = 0; j < 4; j++) {
      int row = j * 16 + r0;
      uint2 hi, lo;
      split4(rA[j], hi, lo);
      *(uint2*)&sAh[row][cv * 4] = hi;
      *(uint2*)&sAl[row][cv * 4] = lo;
      split4(rB1[j], hi, lo);
      *(uint2*)&sB1h[row][cv * 4] = hi;
      *(uint2*)&sB1l[row][cv * 4] = lo;
      split4(rB3[j], hi, lo);
      *(uint2*)&sB3h[row][cv * 4] = hi;
      *(uint2*)&sB3l[row][cv * 4] = lo;
    }
    __syncthreads();

    int kn = k0 + BK;
    if (kn < DIM) {
#pragma unroll
      for (int j = 0; j < 4; j++) {
        int row = j * 16 + r0;
        int r = sRow[row];
        rA[j] = (r >= 0) ? *(const float4*)(x + (size_t)(r >> 1) * DIM + kn + cv * 4)
                         : make_float4(0.f, 0.f, 0.f, 0.f);
        rB1[j] = *(const float4*)(w1b + (size_t)row * DIM + kn + cv * 4);
        rB3[j] = *(const float4*)(w3b + (size_t)row * DIM + kn + cv * 4);
      }
    }

#pragma unroll
    for (int kc = 0; kc < BK; kc += 16) {
      uint32_t ah[2][4], al[2][4];
#pragma unroll
      for (int mf = 0; mf < 2; mf++) {
        ldsm4(ah[mf], &sAh[wm * 32 + mf * 16 + arow][kc + ak]);
        ldsm4(al[mf], &sAl[wm * 32 + mf * 16 + arow][kc + ak]);
      }
#pragma unroll
      for (int ng = 0; ng < 2; ng++) {
        int nb = wn * 32 + ng * 16 + brow;
        uint32_t b1h[4], b1l[4], b3h[4], b3l[4];
        ldsm4(b1h, &sB1h[nb][kc + bk]);
        ldsm4(b1l, &sB1l[nb][kc + bk]);
        ldsm4(b3h, &sB3h[nb][kc + bk]);
        ldsm4(b3l, &sB3l[nb][kc + bk]);
#pragma unroll
        for (int j2 = 0; j2 < 2; j2++) {
          int j = ng * 2 + j2;
#pragma unroll
          for (int mf = 0; mf < 2; mf++) {
            mma16816(acc1[mf][j], ah[mf], b1h[2 * j2], b1h[2 * j2 + 1]);
            mma16816(acc1[mf][j], al[mf], b1h[2 * j2], b1h[2 * j2 + 1]);
            mma16816(acc1[mf][j], ah[mf], b1l[2 * j2], b1l[2 * j2 + 1]);
            mma16816(acc3[mf][j], ah[mf], b3h[2 * j2], b3h[2 * j2 + 1]);
            mma16816(acc3[mf][j], al[mf], b3h[2 * j2], b3h[2 * j2 + 1]);
            mma16816(acc3[mf][j], ah[mf], b3l[2 * j2], b3l[2 * j2 + 1]);
          }
        }
      }
    }
  }

  // epilogue: h = silu(a1) * a3, split to bf16 hi/lo
  int gg = lane >> 2, q = lane & 3;
#pragma unroll
  for (int mf = 0; mf < 2; mf++) {
#pragma unroll
    for (int half = 0; half < 2; half++) {
      int rloc = wm * 32 + mf * 16 + gg + half * 8;
      int r = sRow[rloc];
      if (r < 0) continue;
      size_t base = (size_t)r * HID + n0 + wn * 32;
#pragma unroll
      for (int j = 0; j < 4; j++) {
        float a1 = acc1[mf][j][half * 2 + 0];
        float b1 = acc1[mf][j][half * 2 + 1];
        float a3 = acc3[mf][j][half * 2 + 0];
        float b3 = acc3[mf][j][half * 2 + 1];
        float h0 = (a1 / (1.f + expf(-a1))) * a3;
        float h1 = (b1 / (1.f + expf(-b1))) * b3;
        uint32_t hi, lo;
        split2(h0, h1, hi, lo);
        size_t off = base + j * 8 + 2 * q;
        *(uint32_t*)&g_hh[off] = hi;
        *(uint32_t*)&g_hl[off] = lo;
      }
    }
  }
}

// ---------------- FFN2: ye = h w2^T ----------------
__global__ __launch_bounds__(128, 3) void ffn2_kernel(const float* __restrict__ w2) {
  int e = blockIdx.z;
  int ne = g_cnt[e];
  int m0 = blockIdx.y * BM;
  if (m0 >= ne) return;
  int n0 = blockIdx.x * BN;

  __shared__ __align__(16) __nv_bfloat16 sAh[BM][BKP], sAl[BM][BKP];
  __shared__ __align__(16) __nv_bfloat16 sBh[BN][BKP], sBl[BN][BKP];
  __shared__ int sRow[BM];

  int tid = threadIdx.x;
  int lane = tid & 31, warp = tid >> 5;
  int wm = warp >> 1, wn = warp & 1;

  if (tid < BM) {
    int i = m0 + tid;
    sRow[tid] = (i < ne) ? g_list[e * T_TOK + i] : -1;
  }
  __syncthreads();

  int arow = (lane & 7) + ((lane >> 3) & 1) * 8;
  int ak = (lane >> 4) * 8;
  int brow = (lane & 7) + (lane >> 4) * 8;
  int bk = ((lane >> 3) & 1) * 8;

  const float* w2b = w2 + ((size_t)e * DIM + n0) * HID;

  // A staging (bf16 hi/lo direct copy): 2 chunks per array per thread
  int ar0 = tid >> 2, acv = tid & 3;
  // B staging (fp32 convert): 4 chunks per thread
  int br0 = tid >> 3, bcv = tid & 7;

  float acc[2][4][4];
#pragma unroll
  for (int a = 0; a < 2; a++)
#pragma unroll
    for (int b = 0; b < 4; b++)
#pragma unroll
      for (int c = 0; c < 4; c++) acc[a][b][c] = 0.f;

  uint4 rAh[2], rAl[2];
  float4 rB[4];
  const uint4 z4 = make_uint4(0u, 0u, 0u, 0u);
#pragma unroll
  for (int j = 0; j < 2; j++) {
    int row = j * 32 + ar0;
    int r = sRow[row];
    rAh[j] = (r >= 0) ? *(const uint4*)(g_hh + (size_t)r * HID + acv * 8) : z4;
    rAl[j] = (r >= 0) ? *(const uint4*)(g_hl + (size_t)r * HID + acv * 8) : z4;
  }
#pragma unroll
  for (int j = 0; j < 4; j++) {
    int row = j * 16 + br0;
    rB[j] = *(const float4*)(w2b + (size_t)row * HID + bcv * 4);
  }

  for (int k0 = 0; k0 < HID; k0 += BK) {
    __syncthreads();
#pragma unroll
    for (int j = 0; j < 2; j++) {
      int row = j * 32 + ar0;
      *(uint4*)&sAh[row][acv * 8] = rAh[j];
      *(uint4*)&sAl[row][acv * 8] = rAl[j];
    }
#pragma unroll
    for (int j = 0; j < 4; j++) {
      int row = j * 16 + br0;
      uint2 hi, lo;
      split4(rB[j], hi, lo);
      *(uint2*)&sBh[row][bcv * 4] = hi;
      *(uint2*)&sBl[row][bcv * 4] = lo;
    }
    __syncthreads();

    int kn = k0 + BK;
    if (kn < HID) {
#pragma unroll
      for (int j = 0; j < 2; j++) {
        int row = j * 32 + ar0;
        int r = sRow[row];
        rAh[j] = (r >= 0) ? *(const uint4*)(g_hh + (size_t)r * HID + kn + acv * 8) : z4;
        rAl[j] = (r >= 0) ? *(const uint4*)(g_hl + (size_t)r * HID + kn + acv * 8) : z4;
      }
#pragma unroll
      for (int j = 0; j < 4; j++) {
        int row = j * 16 + br0;
        rB[j] = *(const float4*)(w2b + (size_t)row * HID + kn + bcv * 4);
      }
    }

#pragma unroll
    for (int kc = 0; kc < BK; kc += 16) {
      uint32_t ah[2][4], al[2][4];
#pragma unroll
      for (int mf = 0; mf < 2; mf++) {
        ldsm4(ah[mf], &sAh[wm * 32 + mf * 16 + arow][kc + ak]);
        ldsm4(al[mf], &sAl[wm * 32 + mf * 16 + arow][kc + ak]);
      }
#pragma unroll
      for (int ng = 0; ng < 2; ng++) {
        int nb = wn * 32 + ng * 16 + brow;
        uint32_t bh[4], bl[4];
        ldsm4(bh, &sBh[nb][kc + bk]);
        ldsm4(bl, &sBl[nb][kc + bk]);
#pragma unroll
        for (int j2 = 0; j2 < 2; j2++) {
          int j = ng * 2 + j2;
#pragma unroll
          for (int mf = 0; mf < 2; mf++) {
            mma16816(acc[mf][j], ah[mf], bh[2 * j2], bh[2 * j2 + 1]);
            mma16816(acc[mf][j], al[mf], bh[2 * j2], bh[2 * j2 + 1]);
            mma16816(acc[mf][j], ah[mf], bl[2 * j2], bl[2 * j2 + 1]);
          }
        }
      }
    }
  }

  int gg = lane >> 2, q = lane & 3;
#pragma unroll
  for (int mf = 0; mf < 2; mf++) {
#pragma unroll
    for (int half = 0; half < 2; half++) {
      int rloc = wm * 32 + mf * 16 + gg + half * 8;
      int r = sRow[rloc];
      if (r < 0) continue;
      float* yrow = g_ye + (size_t)r * DIM + n0 + wn * 32;
#pragma unroll
      for (int j = 0; j < 4; j++) {
        *(float2*)(yrow + j * 8 + 2 * q) =
            make_float2(acc[mf][j][half * 2 + 0], acc[mf][j][half * 2 + 1]);
      }
    }
  }
}

__global__ void combine_kernel(float* __restrict__ out) {
  int idx = blockIdx.x * 256 + threadIdx.x;
  int t = idx >> 10;
  int d = idx & 1023;
  out[idx] = g_wpair[2 * t] * g_ye[(size_t)(2 * t) * DIM + d] +
             g_wpair[2 * t + 1] * g_ye[(size_t)(2 * t + 1) * DIM + d];
}

// ---------------- launch ----------------
extern "C" void kernel_launch(void* const* d_in, const int* in_sizes, int n_in,
                              void* d_out, int out_size) {
  const float* x = (const float*)d_in[0];
  const float* gw = (const float*)d_in[1];
  const float* w1 = (const float*)d_in[2];
  const float* w2 = (const float*)d_in[3];
  const float* w3 = (const float*)d_in[4];
  float* out = (float*)d_out;

  reset_kernel<<<1, 32>>>();
  gate_kernel<<<T_TOK / 4, 128>>>(x, gw);
  ffn1_kernel<<<dim3(HID / BN, T_TOK / BM, NE), 128>>>(x, w1, w3);
  ffn2_kernel<<<dim3(DIM / BN, T_TOK / BM, NE), 128>>>(w2);
  combine_kernel<<<(T_TOK * DIM) / 256, 256>>>(out);
}